// round 16
// baseline (speedup 1.0000x reference)
#include <cuda_runtime.h>
#include <cuda_bf16.h>
#include <math.h>
#include <stdint.h>

// Problem constants
#define BATCH 2
#define SEQ   2048
#define EMB   1024
#define HEADS 16
#define HDIM  64
#define ROWS  (BATCH * SEQ)   // 4096
#define LOG2E 1.4426950408889634f

// -------------------- scratch (allocation-free: device globals) --------------------
__device__ float g_Q[ROWS * EMB];
__device__ float g_K[ROWS * EMB];
__device__ float g_V[ROWS * EMB];
__device__ float g_O[ROWS * EMB];          // attention out, tf32-rounded
__device__ float g_Xr[ROWS * EMB];         // tf32-rounded X
__device__ float g_Wr[4 * EMB * EMB];      // tf32-rounded Wq,Wk,Wv,Wo

// -------------------- helpers --------------------
__device__ __forceinline__ float to_tf32(float x) {
    float r; asm("cvt.rna.tf32.f32 %0, %1;" : "=f"(r) : "f"(x)); return r;
}
__device__ __forceinline__ unsigned to_tf32u(float x) {
    unsigned r; asm("cvt.rna.tf32.f32 %0, %1;" : "=r"(r) : "f"(x)); return r;
}
__device__ __forceinline__ float ex2f(float x) {
    float r; asm("ex2.approx.ftz.f32 %0, %1;" : "=f"(r) : "f"(x)); return r;
}
__device__ __forceinline__ void mma_tf32(float d[4], const unsigned a[4],
                                         const unsigned b[2], const float c[4]) {
    asm volatile(
        "mma.sync.aligned.m16n8k8.row.col.f32.tf32.tf32.f32 "
        "{%0,%1,%2,%3}, {%4,%5,%6,%7}, {%8,%9}, {%10,%11,%12,%13};"
        : "=f"(d[0]), "=f"(d[1]), "=f"(d[2]), "=f"(d[3])
        : "r"(a[0]), "r"(a[1]), "r"(a[2]), "r"(a[3]),
          "r"(b[0]), "r"(b[1]),
          "f"(c[0]), "f"(c[1]), "f"(c[2]), "f"(c[3]));
}
__device__ __forceinline__ void cp_async16(unsigned saddr, const void* gptr) {
    asm volatile("cp.async.cg.shared.global [%0], [%1], 16;" :: "r"(saddr), "l"(gptr));
}
__device__ __forceinline__ void cp_commit() { asm volatile("cp.async.commit_group;"); }
__device__ __forceinline__ void cp_wait1()  { asm volatile("cp.async.wait_group 1;"); }
__device__ __forceinline__ void cp_wait0()  { asm volatile("cp.async.wait_group 0;"); }

// ==================================================================================
// Prepass: tf32-round X and the four weight matrices.
// grid.y: 0=X, 1..4=Wq,Wk,Wv,Wo
// ==================================================================================
__global__ __launch_bounds__(256)
void round_tf32_kernel(const float* __restrict__ X,
                       const float* __restrict__ Wq, const float* __restrict__ Wk,
                       const float* __restrict__ Wv, const float* __restrict__ Wo)
{
    const int seg = blockIdx.y;
    const float* src; float* dst; int n4;
    if (seg == 0) { src = X; dst = g_Xr; n4 = ROWS * EMB / 4; }
    else {
        src = (seg == 1) ? Wq : (seg == 2) ? Wk : (seg == 3) ? Wv : Wo;
        dst = g_Wr + (size_t)(seg - 1) * EMB * EMB;
        n4 = EMB * EMB / 4;
    }
    for (int i = blockIdx.x * 256 + threadIdx.x; i < n4; i += gridDim.x * 256) {
        float4 v = ((const float4*)src)[i];
        v.x = to_tf32(v.x); v.y = to_tf32(v.y);
        v.z = to_tf32(v.z); v.w = to_tf32(v.w);
        ((float4*)dst)[i] = v;
    }
}

// ==================================================================================
// tf32 GEMM via raw mma.sync m16n8k8: C = A @ B^T (+bias)
// CTA tile 64x256, BK=32, 8 warps, warp tile 32x64 (2 m16 x 8 n8).
// 2-stage cp.async pipeline, 2 CTAs/SM. Padded stride 36 -> conflict-free LDS.
// ==================================================================================
#define GBM 64
#define GBN 256
#define GLD 36
#define A_F (GBM * GLD)                 // 2304 floats
#define B_F (GBN * GLD)                 // 9216 floats
#define STAGE_F (A_F + B_F)             // 11520 floats
#define GEMM_SMEM_BYTES (2 * STAGE_F * 4)   // 92160

__device__ __forceinline__
void gemm_v4_body(const float* __restrict__ A, const float* __restrict__ B,
                  const float* __restrict__ bias, float* __restrict__ C,
                  int m0, int n0, float* sm, int round_out)
{
    const unsigned sm_u32 = (unsigned)__cvta_generic_to_shared(sm);

    const int tid  = threadIdx.x;
    const int warp = tid >> 5;
    const int lane = tid & 31;
    const int gr = lane >> 2;     // 0..7
    const int j  = lane & 3;      // 0..3
    const int wm = warp & 1;      // 2 warp-rows of 32
    const int wn = warp >> 1;     // 4 warp-cols of 64

    float c[2][8][4];
#pragma unroll
    for (int mt = 0; mt < 2; mt++)
#pragma unroll
        for (int nt = 0; nt < 8; nt++)
#pragma unroll
            for (int p = 0; p < 4; p++) c[mt][nt][p] = 0.0f;

    const int NT = EMB / 32;   // 32 k-tiles

    auto load_stage = [&](int t) {
        const unsigned sb = sm_u32 + (unsigned)(t & 1) * STAGE_F * 4u;
        const int k0 = t * 32;
        // A: 64 rows x 32 floats = 512 x 16B
#pragma unroll
        for (int rep = 0; rep < 2; rep++) {
            const int id = rep * 256 + tid;
            const int row = id >> 3, c4 = (id & 7) << 2;
            cp_async16(sb + (unsigned)(row * GLD + c4) * 4u,
                       A + (size_t)(m0 + row) * EMB + k0 + c4);
        }
        // B: 256 rows x 32 floats = 2048 x 16B
#pragma unroll
        for (int rep = 0; rep < 8; rep++) {
            const int id = rep * 256 + tid;
            const int row = id >> 3, c4 = (id & 7) << 2;
            cp_async16(sb + (unsigned)(A_F + row * GLD + c4) * 4u,
                       B + (size_t)(n0 + row) * EMB + k0 + c4);
        }
        cp_commit();
    };

    load_stage(0);
    load_stage(1);

    for (int t = 0; t < NT; t++) {
        if (t + 1 < NT) cp_wait1(); else cp_wait0();
        __syncthreads();

        const unsigned* As = (const unsigned*)(sm + (t & 1) * STAGE_F);
        const unsigned* Bs = As + A_F;
        const unsigned* Abase = As + (wm * 32 + gr) * GLD + j;
        const unsigned* Bbase = Bs + (wn * 64 + gr) * GLD + j;

#pragma unroll
        for (int ks = 0; ks < 4; ks++) {
            unsigned a[2][4];
#pragma unroll
            for (int mt = 0; mt < 2; mt++) {
                const unsigned* ap = Abase + mt * 16 * GLD + ks * 8;
                a[mt][0] = ap[0];
                a[mt][1] = ap[8 * GLD];
                a[mt][2] = ap[4];
                a[mt][3] = ap[8 * GLD + 4];
            }
            unsigned b[8][2];
#pragma unroll
            for (int nt = 0; nt < 8; nt++) {
                const unsigned* bp = Bbase + nt * 8 * GLD + ks * 8;
                b[nt][0] = bp[0];
                b[nt][1] = bp[4];
            }
#pragma unroll
            for (int mt = 0; mt < 2; mt++)
#pragma unroll
                for (int nt = 0; nt < 8; nt++)
                    mma_tf32(c[mt][nt], a[mt], b[nt], c[mt][nt]);
        }
        __syncthreads();

        if (t + 2 < NT) load_stage(t + 2);
    }

    // ---- epilogue ----
#pragma unroll
    for (int mt = 0; mt < 2; mt++) {
        const int r = m0 + wm * 32 + mt * 16 + gr;
        float* C0 = C + (size_t)r * EMB + n0 + wn * 64;
        float* C1 = C0 + (size_t)8 * EMB;
#pragma unroll
        for (int nt = 0; nt < 8; nt++) {
            const int col = nt * 8 + 2 * j;
            float bx = 0.0f, by = 0.0f;
            if (bias) {
                float2 bv = *(const float2*)(bias + n0 + wn * 64 + col);
                bx = bv.x; by = bv.y;
            }
            float2 v0, v1;
            v0.x = c[mt][nt][0] + bx;  v0.y = c[mt][nt][1] + by;
            v1.x = c[mt][nt][2] + bx;  v1.y = c[mt][nt][3] + by;
            if (round_out) {
                v0.x = to_tf32(v0.x); v0.y = to_tf32(v0.y);
                v1.x = to_tf32(v1.x); v1.y = to_tf32(v1.y);
            }
            *(float2*)(C0 + col) = v0;
            *(float2*)(C1 + col) = v1;
        }
    }
}

// qkv: grid (1024/256, 4096/64, 3) = (4, 64, 3)
__global__ __launch_bounds__(256, 2)
void qkv_gemm_kernel(const float* __restrict__ bq, const float* __restrict__ bk,
                     const float* __restrict__ bv)
{
    extern __shared__ float sm[];
    const int z = blockIdx.z;
    const float* W = g_Wr + (size_t)z * EMB * EMB;
    const float* bias = (z == 0) ? bq : (z == 1) ? bk : bv;
    float* C = (z == 0) ? g_Q : (z == 1) ? g_K : g_V;
    gemm_v4_body(g_Xr, W, bias, C, blockIdx.y * GBM, blockIdx.x * GBN, sm, 1);
}

__global__ __launch_bounds__(256, 2)
void oproj_gemm_kernel(float* __restrict__ out)
{
    extern __shared__ float sm[];
    gemm_v4_body(g_O, g_Wr + (size_t)3 * EMB * EMB, nullptr, out,
                 blockIdx.y * GBM, blockIdx.x * GBN, sm, 0);
}

// ==================================================================================
// Flash attention, register-resident mma.sync tf32, log2-domain softmax.
// Q pre-scaled by scale*log2e; bias folded via FMA(bias, log2e); exp = MUFU.EX2.
// 2-stage cp.async K/V pipeline, grid (S/128, B*H), 256 thr, 2 CTAs/SM.
// ==================================================================================
#define LDK 68
#define LDV 72
#define AKV_FLOATS (64 * LDK + 64 * LDV)
#define ATTN_SMEM_BYTES (2 * AKV_FLOATS * 4)

__global__ __launch_bounds__(256, 2)
void attn_mma_kernel(const float* __restrict__ Q, const float* __restrict__ K,
                     const float* __restrict__ V, const float* __restrict__ bias,
                     float* __restrict__ O)
{
    extern __shared__ unsigned skv[];
    const unsigned skv_u32 = (unsigned)__cvta_generic_to_shared(skv);

    const int bh = blockIdx.y;
    const int b = bh >> 4;
    const int h = bh & 15;
    const int q0 = blockIdx.x * 128;

    const int tid  = threadIdx.x;
    const int warp = tid >> 5;
    const int lane = tid & 31;
    const int gr = lane >> 2;
    const int j  = lane & 3;

    const int qr = q0 + warp * 16 + gr;
    const float qscale = 0.125f * LOG2E;   // fold softmax scale AND log2e into Q

    const float* Kbase0 = K + ((size_t)(b * SEQ)) * EMB + h * HDIM;
    const float* Vbase0 = V + ((size_t)(b * SEQ)) * EMB + h * HDIM;

    auto load_kv = [&](int k0, int stg) {
        const unsigned base = skv_u32 + (unsigned)stg * AKV_FLOATS * 4u;
        const float* Kb = Kbase0 + (size_t)k0 * EMB;
        const float* Vb = Vbase0 + (size_t)k0 * EMB;
#pragma unroll
        for (int rep = 0; rep < 4; rep++) {
            const int idx = rep * 256 + tid;
            const int row = idx >> 4;
            const int c4  = (idx & 15) << 2;
            cp_async16(base + (unsigned)(row * LDK + c4) * 4u, Kb + (size_t)row * EMB + c4);
            cp_async16(base + (unsigned)(64 * LDK + row * LDV + c4) * 4u, Vb + (size_t)row * EMB + c4);
        }
    };

    unsigned qa[8][4];
    {
        const float* Qb  = Q + ((size_t)(b * SEQ) + qr) * EMB + h * HDIM;
        const float* Qb2 = Qb + (size_t)8 * EMB;
#pragma unroll
        for (int kk = 0; kk < 8; kk++) {
            qa[kk][0] = to_tf32u(Qb [kk * 8 + j    ] * qscale);
            qa[kk][1] = to_tf32u(Qb2[kk * 8 + j    ] * qscale);
            qa[kk][2] = to_tf32u(Qb [kk * 8 + j + 4] * qscale);
            qa[kk][3] = to_tf32u(Qb2[kk * 8 + j + 4] * qscale);
        }
    }

    float o[8][4];
#pragma unroll
    for (int n = 0; n < 8; n++)
#pragma unroll
        for (int p = 0; p < 4; p++) o[n][p] = 0.0f;
    float m0 = -INFINITY, m1 = -INFINITY;   // in log2 domain
    float l0 = 0.0f, l1 = 0.0f;

    const float* brow0 = bias + ((size_t)h * SEQ + qr) * SEQ;
    const float* brow1 = brow0 + (size_t)8 * SEQ;

    const int NT = SEQ / 64;
    load_kv(0, 0);
    cp_commit();

    for (int kt = 0; kt < NT; kt++) {
        const int k0 = kt * 64;
        if (kt + 1 < NT) {
            load_kv((kt + 1) * 64, (kt + 1) & 1);
            cp_commit();
            cp_wait1();
        } else {
            cp_wait0();
        }
        __syncthreads();

        const unsigned* sK = skv + (kt & 1) * AKV_FLOATS;
        const unsigned* sV = sK + 64 * LDK;

        // ---- S(log2) = (Q*qscale) @ K^T ----
        float s[8][4];
#pragma unroll
        for (int n = 0; n < 8; n++) {
            s[n][0] = s[n][1] = s[n][2] = s[n][3] = 0.0f;
            const unsigned* kbase = sK + (n * 8 + gr) * LDK;
#pragma unroll
            for (int kk = 0; kk < 8; kk++) {
                unsigned bf[2];
                bf[0] = kbase[kk * 8 + j];
                bf[1] = kbase[kk * 8 + j + 4];
                mma_tf32(s[n], qa[kk], bf, s[n]);
            }
        }

        // ---- bias (x log2e, fused FMA) + online softmax in log2 domain ----
        float tm0 = -INFINITY, tm1 = -INFINITY;
#pragma unroll
        for (int n = 0; n < 8; n++) {
            float2 b0 = *(const float2*)(brow0 + k0 + n * 8 + 2 * j);
            float2 b1 = *(const float2*)(brow1 + k0 + n * 8 + 2 * j);
            s[n][0] = fmaf(b0.x, LOG2E, s[n][0]);
            s[n][1] = fmaf(b0.y, LOG2E, s[n][1]);
            s[n][2] = fmaf(b1.x, LOG2E, s[n][2]);
            s[n][3] = fmaf(b1.y, LOG2E, s[n][3]);
            tm0 = fmaxf(tm0, fmaxf(s[n][0], s[n][1]));
            tm1 = fmaxf(tm1, fmaxf(s[n][2], s[n][3]));
        }
        tm0 = fmaxf(tm0, __shfl_xor_sync(0xffffffffu, tm0, 1));
        tm0 = fmaxf(tm0, __shfl_xor_sync(0xffffffffu, tm0, 2));
        tm1 = fmaxf(tm1, __shfl_xor_sync(0xffffffffu, tm1, 1));
        tm1 = fmaxf(tm1, __shfl_xor_sync(0xffffffffu, tm1, 2));

        const float mn0 = fmaxf(m0, tm0);
        const float mn1 = fmaxf(m1, tm1);
        const float al0 = ex2f(m0 - mn0);
        const float al1 = ex2f(m1 - mn1);
        float rs0 = 0.0f, rs1 = 0.0f;
#pragma unroll
        for (int n = 0; n < 8; n++) {
            s[n][0] = ex2f(s[n][0] - mn0);
            s[n][1] = ex2f(s[n][1] - mn0);
            s[n][2] = ex2f(s[n][2] - mn1);
            s[n][3] = ex2f(s[n][3] - mn1);
            rs0 += s[n][0] + s[n][1];
            rs1 += s[n][2] + s[n][3];
        }
        rs0 += __shfl_xor_sync(0xffffffffu, rs0, 1);
        rs0 += __shfl_xor_sync(0xffffffffu, rs0, 2);
        rs1 += __shfl_xor_sync(0xffffffffu, rs1, 1);
        rs1 += __shfl_xor_sync(0xffffffffu, rs1, 2);
        l0 = l0 * al0 + rs0;  m0 = mn0;
        l1 = l1 * al1 + rs1;  m1 = mn1;

        // ---- O rescale, skipped warp-uniformly when no row's max moved ----
        if (__any_sync(0xffffffffu, (al0 != 1.0f) | (al1 != 1.0f))) {
#pragma unroll
            for (int n = 0; n < 8; n++) {
                o[n][0] *= al0; o[n][1] *= al0;
                o[n][2] *= al1; o[n][3] *= al1;
            }
        }

        // ---- PV: C-layout -> A-layout permute, then mma into O ----
        const int src1 = (lane & ~3) | (j >> 1);
        const int src2 = src1 + 2;
        const bool odd = (j & 1);
#pragma unroll
        for (int kk = 0; kk < 8; kk++) {
            float e0 = __shfl_sync(0xffffffffu, s[kk][0], src1);
            float o0 = __shfl_sync(0xffffffffu, s[kk][1], src1);
            float e1 = __shfl_sync(0xffffffffu, s[kk][2], src1);
            float o1 = __shfl_sync(0xffffffffu, s[kk][3], src1);
            float e2 = __shfl_sync(0xffffffffu, s[kk][0], src2);
            float o2 = __shfl_sync(0xffffffffu, s[kk][1], src2);
            float e3 = __shfl_sync(0xffffffffu, s[kk][2], src2);
            float o3 = __shfl_sync(0xffffffffu, s[kk][3], src2);
            unsigned pa[4];
            pa[0] = to_tf32u(odd ? o0 : e0);
            pa[1] = to_tf32u(odd ? o1 : e1);
            pa[2] = to_tf32u(odd ? o2 : e2);
            pa[3] = to_tf32u(odd ? o3 : e3);

            const unsigned* vb0 = sV + (kk * 8 + j) * LDV + gr;
            const unsigned* vb1 = vb0 + 4 * LDV;
#pragma unroll
            for (int n = 0; n < 8; n++) {
                unsigned bf[2];
                bf[0] = vb0[n * 8];
                bf[1] = vb1[n * 8];
                mma_tf32(o[n], pa, bf, o[n]);
            }
        }
        __syncthreads();
    }

    // ---- normalize + tf32-round + write ----
    const float inv0 = 1.0f / l0;
    const float inv1 = 1.0f / l1;
    float* Ob  = O + ((size_t)(b * SEQ) + qr) * EMB + h * HDIM;
    float* Ob2 = Ob + (size_t)8 * EMB;
#pragma unroll
    for (int n = 0; n < 8; n++) {
        float2 v0, v1;
        v0.x = to_tf32(o[n][0] * inv0);  v0.y = to_tf32(o[n][1] * inv0);
        v1.x = to_tf32(o[n][2] * inv1);  v1.y = to_tf32(o[n][3] * inv1);
        *(float2*)(Ob  + n * 8 + 2 * j) = v0;
        *(float2*)(Ob2 + n * 8 + 2 * j) = v1;
    }
}

// ==================================================================================
// Launch
// ==================================================================================
extern "C" void kernel_launch(void* const* d_in, const int* in_sizes, int n_in,
                              void* d_out, int out_size)
{
    const float* X    = (const float*)d_in[0];
    const float* bias = (const float*)d_in[1];
    const float* Wq   = (const float*)d_in[2];
    const float* bq   = (const float*)d_in[3];
    const float* Wk   = (const float*)d_in[4];
    const float* bk   = (const float*)d_in[5];
    const float* Wv   = (const float*)d_in[6];
    const float* bv   = (const float*)d_in[7];
    const float* Wo   = (const float*)d_in[8];
    float* out = (float*)d_out;

    float *Qp, *Kp, *Vp, *Op;
    cudaGetSymbolAddress((void**)&Qp, g_Q);
    cudaGetSymbolAddress((void**)&Kp, g_K);
    cudaGetSymbolAddress((void**)&Vp, g_V);
    cudaGetSymbolAddress((void**)&Op, g_O);

    cudaFuncSetAttribute(qkv_gemm_kernel,
                         cudaFuncAttributeMaxDynamicSharedMemorySize, GEMM_SMEM_BYTES);
    cudaFuncSetAttribute(oproj_gemm_kernel,
                         cudaFuncAttributeMaxDynamicSharedMemorySize, GEMM_SMEM_BYTES);
    cudaFuncSetAttribute(attn_mma_kernel,
                         cudaFuncAttributeMaxDynamicSharedMemorySize, ATTN_SMEM_BYTES);

    // 1. tf32-round X and W
    dim3 rgrid(256, 5);
    round_tf32_kernel<<<rgrid, 256>>>(X, Wq, Wk, Wv, Wo);

    // 2. Q/K/V projections
    dim3 qkvgrid(EMB / GBN, ROWS / GBM, 3);  // (4, 64, 3)
    qkv_gemm_kernel<<<qkvgrid, 256, GEMM_SMEM_BYTES>>>(bq, bk, bv);

    // 3. attention
    dim3 agrid(SEQ / 128, BATCH * HEADS);    // (16, 32)
    attn_mma_kernel<<<agrid, 256, ATTN_SMEM_BYTES>>>(Qp, Kp, Vp, bias, Op);

    // 4. output projection
    dim3 ogrid(EMB / GBN, ROWS / GBM);       // (4, 64)
    oproj_gemm_kernel<<<ogrid, 256, GEMM_SMEM_BYTES>>>(out);
}

// round 17
// speedup vs baseline: 1.0470x; 1.0470x over previous
#include <cuda_runtime.h>
#include <cuda_bf16.h>
#include <math.h>
#include <stdint.h>

// Problem constants
#define BATCH 2
#define SEQ   2048
#define EMB   1024
#define HEADS 16
#define HDIM  64
#define ROWS  (BATCH * SEQ)   // 4096
#define LOG2E 1.4426950408889634f

// -------------------- scratch (allocation-free: device globals) --------------------
__device__ float g_Q[ROWS * EMB];
__device__ float g_K[ROWS * EMB];
__device__ float g_V[ROWS * EMB];
__device__ float g_O[ROWS * EMB];          // attention out, tf32-rounded
__device__ float g_Xr[ROWS * EMB];         // tf32-rounded X
__device__ float g_Wr[4 * EMB * EMB];      // tf32-rounded Wq,Wk,Wv,Wo

// -------------------- helpers --------------------
__device__ __forceinline__ float to_tf32(float x) {
    float r; asm("cvt.rna.tf32.f32 %0, %1;" : "=f"(r) : "f"(x)); return r;
}
__device__ __forceinline__ unsigned to_tf32u(float x) {
    unsigned r; asm("cvt.rna.tf32.f32 %0, %1;" : "=r"(r) : "f"(x)); return r;
}
__device__ __forceinline__ float ex2f(float x) {
    float r; asm("ex2.approx.ftz.f32 %0, %1;" : "=f"(r) : "f"(x)); return r;
}
__device__ __forceinline__ void mma_tf32(float d[4], const unsigned a[4],
                                         const unsigned b[2], const float c[4]) {
    asm volatile(
        "mma.sync.aligned.m16n8k8.row.col.f32.tf32.tf32.f32 "
        "{%0,%1,%2,%3}, {%4,%5,%6,%7}, {%8,%9}, {%10,%11,%12,%13};"
        : "=f"(d[0]), "=f"(d[1]), "=f"(d[2]), "=f"(d[3])
        : "r"(a[0]), "r"(a[1]), "r"(a[2]), "r"(a[3]),
          "r"(b[0]), "r"(b[1]),
          "f"(c[0]), "f"(c[1]), "f"(c[2]), "f"(c[3]));
}
__device__ __forceinline__ void cp_async16(unsigned saddr, const void* gptr) {
    asm volatile("cp.async.cg.shared.global [%0], [%1], 16;" :: "r"(saddr), "l"(gptr));
}
__device__ __forceinline__ void cp_commit() { asm volatile("cp.async.commit_group;"); }
__device__ __forceinline__ void cp_wait2()  { asm volatile("cp.async.wait_group 2;"); }
__device__ __forceinline__ void cp_wait1()  { asm volatile("cp.async.wait_group 1;"); }
__device__ __forceinline__ void cp_wait0()  { asm volatile("cp.async.wait_group 0;"); }

// ==================================================================================
// Prepass: tf32-round X and the four weight matrices.
// grid.y: 0=X, 1..4=Wq,Wk,Wv,Wo
// ==================================================================================
__global__ __launch_bounds__(256)
void round_tf32_kernel(const float* __restrict__ X,
                       const float* __restrict__ Wq, const float* __restrict__ Wk,
                       const float* __restrict__ Wv, const float* __restrict__ Wo)
{
    const int seg = blockIdx.y;
    const float* src; float* dst; int n4;
    if (seg == 0) { src = X; dst = g_Xr; n4 = ROWS * EMB / 4; }
    else {
        src = (seg == 1) ? Wq : (seg == 2) ? Wk : (seg == 3) ? Wv : Wo;
        dst = g_Wr + (size_t)(seg - 1) * EMB * EMB;
        n4 = EMB * EMB / 4;
    }
    for (int i = blockIdx.x * 256 + threadIdx.x; i < n4; i += gridDim.x * 256) {
        float4 v = ((const float4*)src)[i];
        v.x = to_tf32(v.x); v.y = to_tf32(v.y);
        v.z = to_tf32(v.z); v.w = to_tf32(v.w);
        ((float4*)dst)[i] = v;
    }
}

// ==================================================================================
// tf32 GEMM via raw mma.sync m16n8k8 (round-14 config: fastest measured).
// CTA tile 128x256, BK=32, 8 warps, warp tile 64x64 (4 m16 x 8 n8).
// 3-stage cp.async pipeline. Padded smem stride 36 -> conflict-free fragment LDS.
// ==================================================================================
#define GLD 36
#define A_F (128 * GLD)                 // 4608 floats
#define B_F (256 * GLD)                 // 9216 floats
#define STAGE_F (A_F + B_F)             // 13824 floats
#define GEMM_SMEM_BYTES (3 * STAGE_F * 4)   // 165888

__device__ __forceinline__
void gemm_v3_body(const float* __restrict__ A, const float* __restrict__ B,
                  const float* __restrict__ bias, float* __restrict__ C,
                  int m0, int n0, float* sm, int round_out)
{
    const unsigned sm_u32 = (unsigned)__cvta_generic_to_shared(sm);

    const int tid  = threadIdx.x;
    const int warp = tid >> 5;
    const int lane = tid & 31;
    const int gr = lane >> 2;     // 0..7
    const int j  = lane & 3;      // 0..3
    const int wm = warp & 1;      // 2 warp-rows of 64
    const int wn = warp >> 1;     // 4 warp-cols of 64

    float c[4][8][4];
#pragma unroll
    for (int mt = 0; mt < 4; mt++)
#pragma unroll
        for (int nt = 0; nt < 8; nt++)
#pragma unroll
            for (int p = 0; p < 4; p++) c[mt][nt][p] = 0.0f;

    const int NT = EMB / 32;   // 32 k-tiles

    auto load_stage = [&](int t) {
        const unsigned sb = sm_u32 + (unsigned)(t % 3) * STAGE_F * 4u;
        const int k0 = t * 32;
        // A: 128 rows x 32 floats = 1024 x 16B
#pragma unroll
        for (int rep = 0; rep < 4; rep++) {
            const int id = rep * 256 + tid;
            const int row = id >> 3, c4 = (id & 7) << 2;
            cp_async16(sb + (unsigned)(row * GLD + c4) * 4u,
                       A + (size_t)(m0 + row) * EMB + k0 + c4);
        }
        // B: 256 rows x 32 floats = 2048 x 16B
#pragma unroll
        for (int rep = 0; rep < 8; rep++) {
            const int id = rep * 256 + tid;
            const int row = id >> 3, c4 = (id & 7) << 2;
            cp_async16(sb + (unsigned)(A_F + row * GLD + c4) * 4u,
                       B + (size_t)(n0 + row) * EMB + k0 + c4);
        }
        cp_commit();
    };

    load_stage(0);
    load_stage(1);
    load_stage(2);

    for (int t = 0; t < NT; t++) {
        const int rem = NT - 1 - t;
        if (rem >= 2) cp_wait2(); else if (rem == 1) cp_wait1(); else cp_wait0();
        __syncthreads();

        const unsigned* As = (const unsigned*)(sm + (t % 3) * STAGE_F);
        const unsigned* Bs = As + A_F;
        const unsigned* Abase = As + (wm * 64 + gr) * GLD + j;
        const unsigned* Bbase = Bs + (wn * 64 + gr) * GLD + j;

#pragma unroll
        for (int ks = 0; ks < 4; ks++) {
            unsigned a[4][4];
#pragma unroll
            for (int mt = 0; mt < 4; mt++) {
                const unsigned* ap = Abase + mt * 16 * GLD + ks * 8;
                a[mt][0] = ap[0];
                a[mt][1] = ap[8 * GLD];
                a[mt][2] = ap[4];
                a[mt][3] = ap[8 * GLD + 4];
            }
            unsigned b[8][2];
#pragma unroll
            for (int nt = 0; nt < 8; nt++) {
                const unsigned* bp = Bbase + nt * 8 * GLD + ks * 8;
                b[nt][0] = bp[0];
                b[nt][1] = bp[4];
            }
#pragma unroll
            for (int mt = 0; mt < 4; mt++)
#pragma unroll
                for (int nt = 0; nt < 8; nt++)
                    mma_tf32(c[mt][nt], a[mt], b[nt], c[mt][nt]);
        }
        __syncthreads();

        if (t + 3 < NT) load_stage(t + 3);
    }

    // ---- epilogue: direct float2 stores, bias from gmem (L2-resident) ----
#pragma unroll
    for (int mt = 0; mt < 4; mt++) {
        const int r = m0 + wm * 64 + mt * 16 + gr;
        float* C0 = C + (size_t)r * EMB + n0 + wn * 64;
        float* C1 = C0 + (size_t)8 * EMB;
#pragma unroll
        for (int nt = 0; nt < 8; nt++) {
            const int col = nt * 8 + 2 * j;
            float bx = 0.0f, by = 0.0f;
            if (bias) {
                float2 bv = *(const float2*)(bias + n0 + wn * 64 + col);
                bx = bv.x; by = bv.y;
            }
            float2 v0, v1;
            v0.x = c[mt][nt][0] + bx;  v0.y = c[mt][nt][1] + by;
            v1.x = c[mt][nt][2] + bx;  v1.y = c[mt][nt][3] + by;
            if (round_out) {
                v0.x = to_tf32(v0.x); v0.y = to_tf32(v0.y);
                v1.x = to_tf32(v1.x); v1.y = to_tf32(v1.y);
            }
            *(float2*)(C0 + col) = v0;
            *(float2*)(C1 + col) = v1;
        }
    }
}

// qkv: grid (1024/256, 4096/128, 3)
__global__ __launch_bounds__(256, 1)
void qkv_gemm_kernel(const float* __restrict__ bq, const float* __restrict__ bk,
                     const float* __restrict__ bv)
{
    extern __shared__ float sm[];
    const int z = blockIdx.z;
    const float* W = g_Wr + (size_t)z * EMB * EMB;
    const float* bias = (z == 0) ? bq : (z == 1) ? bk : bv;
    float* C = (z == 0) ? g_Q : (z == 1) ? g_K : g_V;
    gemm_v3_body(g_Xr, W, bias, C, blockIdx.y * 128, blockIdx.x * 256, sm, 1);
}

__global__ __launch_bounds__(256, 1)
void oproj_gemm_kernel(float* __restrict__ out)
{
    extern __shared__ float sm[];
    gemm_v3_body(g_O, g_Wr + (size_t)3 * EMB * EMB, nullptr, out,
                 blockIdx.y * 128, blockIdx.x * 256, sm, 0);
}

// ==================================================================================
// Flash attention, register-resident mma.sync tf32, log2-domain softmax.
// Q pre-scaled by scale*log2e; bias folded via FMA(bias, log2e); exp = MUFU.EX2.
// 2-stage cp.async K/V pipeline, grid (S/128, B*H), 256 thr, 2 CTAs/SM.
// ==================================================================================
#define LDK 68
#define LDV 72
#define AKV_FLOATS (64 * LDK + 64 * LDV)
#define ATTN_SMEM_BYTES (2 * AKV_FLOATS * 4)

__global__ __launch_bounds__(256, 2)
void attn_mma_kernel(const float* __restrict__ Q, const float* __restrict__ K,
                     const float* __restrict__ V, const float* __restrict__ bias,
                     float* __restrict__ O)
{
    extern __shared__ unsigned skv[];
    const unsigned skv_u32 = (unsigned)__cvta_generic_to_shared(skv);

    const int bh = blockIdx.y;
    const int b = bh >> 4;
    const int h = bh & 15;
    const int q0 = blockIdx.x * 128;

    const int tid  = threadIdx.x;
    const int warp = tid >> 5;
    const int lane = tid & 31;
    const int gr = lane >> 2;
    const int j  = lane & 3;

    const int qr = q0 + warp * 16 + gr;
    const float qscale = 0.125f * LOG2E;   // fold softmax scale AND log2e into Q

    const float* Kbase0 = K + ((size_t)(b * SEQ)) * EMB + h * HDIM;
    const float* Vbase0 = V + ((size_t)(b * SEQ)) * EMB + h * HDIM;

    auto load_kv = [&](int k0, int stg) {
        const unsigned base = skv_u32 + (unsigned)stg * AKV_FLOATS * 4u;
        const float* Kb = Kbase0 + (size_t)k0 * EMB;
        const float* Vb = Vbase0 + (size_t)k0 * EMB;
#pragma unroll
        for (int rep = 0; rep < 4; rep++) {
            const int idx = rep * 256 + tid;
            const int row = idx >> 4;
            const int c4  = (idx & 15) << 2;
            cp_async16(base + (unsigned)(row * LDK + c4) * 4u, Kb + (size_t)row * EMB + c4);
            cp_async16(base + (unsigned)(64 * LDK + row * LDV + c4) * 4u, Vb + (size_t)row * EMB + c4);
        }
    };

    unsigned qa[8][4];
    {
        const float* Qb  = Q + ((size_t)(b * SEQ) + qr) * EMB + h * HDIM;
        const float* Qb2 = Qb + (size_t)8 * EMB;
#pragma unroll
        for (int kk = 0; kk < 8; kk++) {
            qa[kk][0] = to_tf32u(Qb [kk * 8 + j    ] * qscale);
            qa[kk][1] = to_tf32u(Qb2[kk * 8 + j    ] * qscale);
            qa[kk][2] = to_tf32u(Qb [kk * 8 + j + 4] * qscale);
            qa[kk][3] = to_tf32u(Qb2[kk * 8 + j + 4] * qscale);
        }
    }

    float o[8][4];
#pragma unroll
    for (int n = 0; n < 8; n++)
#pragma unroll
        for (int p = 0; p < 4; p++) o[n][p] = 0.0f;
    float m0 = -INFINITY, m1 = -INFINITY;   // in log2 domain
    float l0 = 0.0f, l1 = 0.0f;

    const float* brow0 = bias + ((size_t)h * SEQ + qr) * SEQ;
    const float* brow1 = brow0 + (size_t)8 * SEQ;

    const int NT = SEQ / 64;
    load_kv(0, 0);
    cp_commit();

    for (int kt = 0; kt < NT; kt++) {
        const int k0 = kt * 64;
        if (kt + 1 < NT) {
            load_kv((kt + 1) * 64, (kt + 1) & 1);
            cp_commit();
            cp_wait1();
        } else {
            cp_wait0();
        }
        __syncthreads();

        const unsigned* sK = skv + (kt & 1) * AKV_FLOATS;
        const unsigned* sV = sK + 64 * LDK;

        // ---- S(log2) = (Q*qscale) @ K^T ----
        float s[8][4];
#pragma unroll
        for (int n = 0; n < 8; n++) {
            s[n][0] = s[n][1] = s[n][2] = s[n][3] = 0.0f;
            const unsigned* kbase = sK + (n * 8 + gr) * LDK;
#pragma unroll
            for (int kk = 0; kk < 8; kk++) {
                unsigned bf[2];
                bf[0] = kbase[kk * 8 + j];
                bf[1] = kbase[kk * 8 + j + 4];
                mma_tf32(s[n], qa[kk], bf, s[n]);
            }
        }

        // ---- bias (x log2e, fused FMA) + online softmax in log2 domain ----
        float tm0 = -INFINITY, tm1 = -INFINITY;
#pragma unroll
        for (int n = 0; n < 8; n++) {
            float2 b0 = *(const float2*)(brow0 + k0 + n * 8 + 2 * j);
            float2 b1 = *(const float2*)(brow1 + k0 + n * 8 + 2 * j);
            s[n][0] = fmaf(b0.x, LOG2E, s[n][0]);
            s[n][1] = fmaf(b0.y, LOG2E, s[n][1]);
            s[n][2] = fmaf(b1.x, LOG2E, s[n][2]);
            s[n][3] = fmaf(b1.y, LOG2E, s[n][3]);
            tm0 = fmaxf(tm0, fmaxf(s[n][0], s[n][1]));
            tm1 = fmaxf(tm1, fmaxf(s[n][2], s[n][3]));
        }
        tm0 = fmaxf(tm0, __shfl_xor_sync(0xffffffffu, tm0, 1));
        tm0 = fmaxf(tm0, __shfl_xor_sync(0xffffffffu, tm0, 2));
        tm1 = fmaxf(tm1, __shfl_xor_sync(0xffffffffu, tm1, 1));
        tm1 = fmaxf(tm1, __shfl_xor_sync(0xffffffffu, tm1, 2));

        const float mn0 = fmaxf(m0, tm0);
        const float mn1 = fmaxf(m1, tm1);
        const float al0 = ex2f(m0 - mn0);
        const float al1 = ex2f(m1 - mn1);
        float rs0 = 0.0f, rs1 = 0.0f;
#pragma unroll
        for (int n = 0; n < 8; n++) {
            s[n][0] = ex2f(s[n][0] - mn0);
            s[n][1] = ex2f(s[n][1] - mn0);
            s[n][2] = ex2f(s[n][2] - mn1);
            s[n][3] = ex2f(s[n][3] - mn1);
            rs0 += s[n][0] + s[n][1];
            rs1 += s[n][2] + s[n][3];
        }
        rs0 += __shfl_xor_sync(0xffffffffu, rs0, 1);
        rs0 += __shfl_xor_sync(0xffffffffu, rs0, 2);
        rs1 += __shfl_xor_sync(0xffffffffu, rs1, 1);
        rs1 += __shfl_xor_sync(0xffffffffu, rs1, 2);
        l0 = l0 * al0 + rs0;  m0 = mn0;
        l1 = l1 * al1 + rs1;  m1 = mn1;

        // ---- O rescale, skipped warp-uniformly when no row's max moved ----
        if (__any_sync(0xffffffffu, (al0 != 1.0f) | (al1 != 1.0f))) {
#pragma unroll
            for (int n = 0; n < 8; n++) {
                o[n][0] *= al0; o[n][1] *= al0;
                o[n][2] *= al1; o[n][3] *= al1;
            }
        }

        // ---- PV: C-layout -> A-layout permute, then mma into O ----
        const int src1 = (lane & ~3) | (j >> 1);
        const int src2 = src1 + 2;
        const bool odd = (j & 1);
#pragma unroll
        for (int kk = 0; kk < 8; kk++) {
            float e0 = __shfl_sync(0xffffffffu, s[kk][0], src1);
            float o0 = __shfl_sync(0xffffffffu, s[kk][1], src1);
            float e1 = __shfl_sync(0xffffffffu, s[kk][2], src1);
            float o1 = __shfl_sync(0xffffffffu, s[kk][3], src1);
            float e2 = __shfl_sync(0xffffffffu, s[kk][0], src2);
            float o2 = __shfl_sync(0xffffffffu, s[kk][1], src2);
            float e3 = __shfl_sync(0xffffffffu, s[kk][2], src2);
            float o3 = __shfl_sync(0xffffffffu, s[kk][3], src2);
            unsigned pa[4];
            pa[0] = to_tf32u(odd ? o0 : e0);
            pa[1] = to_tf32u(odd ? o1 : e1);
            pa[2] = to_tf32u(odd ? o2 : e2);
            pa[3] = to_tf32u(odd ? o3 : e3);

            const unsigned* vb0 = sV + (kk * 8 + j) * LDV + gr;
            const unsigned* vb1 = vb0 + 4 * LDV;
#pragma unroll
            for (int n = 0; n < 8; n++) {
                unsigned bf[2];
                bf[0] = vb0[n * 8];
                bf[1] = vb1[n * 8];
                mma_tf32(o[n], pa, bf, o[n]);
            }
        }
        __syncthreads();
    }

    // ---- normalize + tf32-round + write ----
    const float inv0 = 1.0f / l0;
    const float inv1 = 1.0f / l1;
    float* Ob  = O + ((size_t)(b * SEQ) + qr) * EMB + h * HDIM;
    float* Ob2 = Ob + (size_t)8 * EMB;
#pragma unroll
    for (int n = 0; n < 8; n++) {
        float2 v0, v1;
        v0.x = to_tf32(o[n][0] * inv0);  v0.y = to_tf32(o[n][1] * inv0);
        v1.x = to_tf32(o[n][2] * inv1);  v1.y = to_tf32(o[n][3] * inv1);
        *(float2*)(Ob  + n * 8 + 2 * j) = v0;
        *(float2*)(Ob2 + n * 8 + 2 * j) = v1;
    }
}

// ==================================================================================
// Launch
// ==================================================================================
extern "C" void kernel_launch(void* const* d_in, const int* in_sizes, int n_in,
                              void* d_out, int out_size)
{
    const float* X    = (const float*)d_in[0];
    const float* bias = (const float*)d_in[1];
    const float* Wq   = (const float*)d_in[2];
    const float* bq   = (const float*)d_in[3];
    const float* Wk   = (const float*)d_in[4];
    const float* bk   = (const float*)d_in[5];
    const float* Wv   = (const float*)d_in[6];
    const float* bv   = (const float*)d_in[7];
    const float* Wo   = (const float*)d_in[8];
    float* out = (float*)d_out;

    float *Qp, *Kp, *Vp, *Op;
    cudaGetSymbolAddress((void**)&Qp, g_Q);
    cudaGetSymbolAddress((void**)&Kp, g_K);
    cudaGetSymbolAddress((void**)&Vp, g_V);
    cudaGetSymbolAddress((void**)&Op, g_O);

    cudaFuncSetAttribute(qkv_gemm_kernel,
                         cudaFuncAttributeMaxDynamicSharedMemorySize, GEMM_SMEM_BYTES);
    cudaFuncSetAttribute(oproj_gemm_kernel,
                         cudaFuncAttributeMaxDynamicSharedMemorySize, GEMM_SMEM_BYTES);
    cudaFuncSetAttribute(attn_mma_kernel,
                         cudaFuncAttributeMaxDynamicSharedMemorySize, ATTN_SMEM_BYTES);

    // 1. tf32-round X and W
    dim3 rgrid(256, 5);
    round_tf32_kernel<<<rgrid, 256>>>(X, Wq, Wk, Wv, Wo);

    // 2. Q/K/V projections
    dim3 qkvgrid(EMB / 256, ROWS / 128, 3);  // (4, 32, 3)
    qkv_gemm_kernel<<<qkvgrid, 256, GEMM_SMEM_BYTES>>>(bq, bk, bv);

    // 3. attention
    dim3 agrid(SEQ / 128, BATCH * HEADS);    // (16, 32)
    attn_mma_kernel<<<agrid, 256, ATTN_SMEM_BYTES>>>(Qp, Kp, Vp, bias, Op);

    // 4. output projection
    dim3 ogrid(EMB / 256, ROWS / 128);       // (4, 32)
    oproj_gemm_kernel<<<ogrid, 256, GEMM_SMEM_BYTES>>>(out);
}